// round 2
// baseline (speedup 1.0000x reference)
#include <cuda_runtime.h>
#include <cstdint>

// CenterLoss: mean_i ||x[i] - centers[labels[i]]||^2
// B=16384, C=4000, D=512
//
// Inputs (metadata order): x [B*D] float32, labels [B] int32 (JAX x64 off),
//                          centers [C*D] float32
// Output: scalar float32.

#define B_ROWS 16384
#define C_ROWS 4000
#define D_DIM  512
#define D_VEC  (D_DIM / 4)       // 128 float4 per row
#define WARPS_PER_BLOCK 8
#define THREADS (WARPS_PER_BLOCK * 32)

__global__ __launch_bounds__(THREADS)
void center_loss_kernel(const float4* __restrict__ x,
                        const int* __restrict__ labels,
                        const float4* __restrict__ centers,
                        float* __restrict__ out)
{
    const int warp = threadIdx.x >> 5;
    const int lane = threadIdx.x & 31;
    const int row  = blockIdx.x * WARPS_PER_BLOCK + warp;

    float s = 0.0f;
    if (row < B_ROWS) {
        int lab = labels[row];
        // Defensive clamp: if the dtype assumption is wrong we want a finite
        // wrong answer (rel_err signal), not an illegal memory access.
        if (lab < 0) lab = 0;
        if (lab >= C_ROWS) lab = C_ROWS - 1;

        const float4* xr = x       + (size_t)row * D_VEC;
        const float4* cr = centers + (size_t)lab * D_VEC;

        // 128 float4 per row, 32 lanes -> 4 float4 each. Front-batch loads
        // (MLP=8 per lane) so DRAM latency overlaps.
        float4 a0 = xr[lane];
        float4 a1 = xr[lane + 32];
        float4 a2 = xr[lane + 64];
        float4 a3 = xr[lane + 96];
        float4 b0 = cr[lane];
        float4 b1 = cr[lane + 32];
        float4 b2 = cr[lane + 64];
        float4 b3 = cr[lane + 96];

        float dx, dy, dz, dw;
        dx = a0.x - b0.x; dy = a0.y - b0.y; dz = a0.z - b0.z; dw = a0.w - b0.w;
        s += dx*dx + dy*dy + dz*dz + dw*dw;
        dx = a1.x - b1.x; dy = a1.y - b1.y; dz = a1.z - b1.z; dw = a1.w - b1.w;
        s += dx*dx + dy*dy + dz*dz + dw*dw;
        dx = a2.x - b2.x; dy = a2.y - b2.y; dz = a2.z - b2.z; dw = a2.w - b2.w;
        s += dx*dx + dy*dy + dz*dz + dw*dw;
        dx = a3.x - b3.x; dy = a3.y - b3.y; dz = a3.z - b3.z; dw = a3.w - b3.w;
        s += dx*dx + dy*dy + dz*dz + dw*dw;
    }

    // warp reduce
    #pragma unroll
    for (int o = 16; o > 0; o >>= 1)
        s += __shfl_xor_sync(0xFFFFFFFFu, s, o);

    __shared__ float warp_sums[WARPS_PER_BLOCK];
    if (lane == 0) warp_sums[warp] = s;
    __syncthreads();

    if (warp == 0) {
        float v = (lane < WARPS_PER_BLOCK) ? warp_sums[lane] : 0.0f;
        #pragma unroll
        for (int o = 4; o > 0; o >>= 1)
            v += __shfl_xor_sync(0xFFFFFFFFu, v, o);
        if (lane == 0)
            atomicAdd(out, v * (1.0f / (float)B_ROWS));
    }
}

extern "C" void kernel_launch(void* const* d_in, const int* in_sizes, int n_in,
                              void* d_out, int out_size)
{
    const float4* x       = (const float4*)d_in[0];
    const int*    labels  = (const int*)d_in[1];
    const float4* centers = (const float4*)d_in[2];
    float*        out     = (float*)d_out;

    cudaMemsetAsync(out, 0, sizeof(float));

    const int blocks = B_ROWS / WARPS_PER_BLOCK;  // 2048
    center_loss_kernel<<<blocks, THREADS>>>(x, labels, centers, out);
}